// round 13
// baseline (speedup 1.0000x reference)
#include <cuda_runtime.h>
#include <cuda_fp16.h>
#include <cuda_bf16.h>
#include <cstdint>

// Problem constants (fixed by the dataset).
#define TREES 64
#define DNODES 255      // internal nodes per tree (2^8 - 1)
#define KLEAF 256       // leaves per tree
#define MFEAT 512       // features
#define CCLS 8          // classes
#define BATCH 4096

// Blocking: CTA = 256 threads (8 warps = 8 leaf slices) over 64 batch rows.
// Lane l owns rows (bbase+l, bbase+l+32), packed as half2 in smem.
#define ROWS 64
#define TGROUP 4        // trees per CTA -> grid (64, 16) = 1024 CTAs

// Scratch (no cudaMalloc allowed): packed per-node parameters.
// g_node[t*DNODES+d] = { feature_index, half2{5*b1, 5*b1} }.
__device__ uint2 g_node[TREES * DNODES];

// ---------------------------------------------------------------------------
// Preprocess: extract one-hot feature index from W1 rows; pack with half2(5*b1).
// One warp per (t,d) row of 512 floats.
// ---------------------------------------------------------------------------
__global__ void prep_kernel(const float* __restrict__ W1,
                            const float* __restrict__ b1)
{
    int row = blockIdx.x * (blockDim.x >> 5) + (threadIdx.x >> 5);
    if (row >= TREES * DNODES) return;
    int lane = threadIdx.x & 31;

    const float4* w4 = reinterpret_cast<const float4*>(W1 + (size_t)row * MFEAT);
    int idx = 0;
#pragma unroll
    for (int i = 0; i < 4; i++) {
        float4 v = w4[i * 32 + lane];
        int base = (i * 32 + lane) * 4;
        if (v.x != 0.0f) idx = base + 0;
        if (v.y != 0.0f) idx = base + 1;
        if (v.z != 0.0f) idx = base + 2;
        if (v.w != 0.0f) idx = base + 3;
    }
#pragma unroll
    for (int off = 16; off; off >>= 1)
        idx = max(idx, __shfl_xor_sync(0xffffffffu, idx, off));
    if (lane == 0) {
        // sigmoid(10x+10b) = 0.5 + 0.5*tanh(5x+5b)
        __half   h  = __float2half(5.0f * b1[row]);
        __half2  h2 = __half2half2(h);
        g_node[row] = make_uint2((unsigned)idx,
                                 *reinterpret_cast<unsigned*>(&h2));
    }
}

// th = tanh(z) via single MUFU.TANH.
__device__ __forceinline__ float tanhf_hw(float z)
{
    float r;
    asm("tanh.approx.f32 %0, %1;" : "=f"(r) : "f"(z));
    return r;
}

typedef unsigned long long ull;

__device__ __forceinline__ ull pk2(float lo, float hi)
{
    ull r;
    asm("mov.b64 %0, {%1, %2};" : "=l"(r) : "f"(lo), "f"(hi));
    return r;
}
__device__ __forceinline__ ull ffma2(ull a, ull b, ull c)
{
    ull d;
    asm("fma.rn.f32x2 %0, %1, %2, %3;" : "=l"(d) : "l"(a), "l"(b), "l"(c));
    return d;
}
__device__ __forceinline__ ull mul2(ull a, ull b)
{
    ull d;
    asm("mul.rn.f32x2 %0, %1, %2;" : "=l"(d) : "l"(a), "l"(b));
    return d;
}
__device__ __forceinline__ void upk2(ull v, float& lo, float& hi)
{
    asm("mov.b64 {%0, %1}, %2;" : "=f"(lo), "=f"(hi) : "l"(v));
}

#define H2  0x3F0000003F000000ull   // {0.5f, 0.5f}
#define NH2 0xBF000000BF000000ull   // {-0.5f, -0.5f}

// ---------------------------------------------------------------------------
// Main kernel. 256 threads (8 warps = 8 slices), 64 rows as 32 half2 row-pairs.
// xs layout: word index (f<<5) | (lane ^ (f&31)) -> per-node gather is ONE
// LDS.32, conflict-free. Node tables + Cw staged per tree (single-buffered;
// 3 resident CTAs/SM cover the staging latency). Level 6/7 processed one
// level-6 subtree at a time to keep live registers <= 85 (3 CTAs by regs).
// ---------------------------------------------------------------------------
__global__ __launch_bounds__(256, 3)
void forest_kernel(const float* __restrict__ x,
                   const float* __restrict__ Cw,
                   float* __restrict__ out)
{
    extern __shared__ unsigned smem_u[];
    unsigned* xs  = smem_u;                                       // 512*32 words (64 KB)
    uint2*    nd  = reinterpret_cast<uint2*>(smem_u + 512 * 32);  // 258 slots (node d -> d+1)
    float4*   cw  = reinterpret_cast<float4*>(smem_u + 512 * 32 + 258 * 2); // 512 float4

    const int tid   = threadIdx.x;
    const int lane  = tid & 31;
    const int s     = tid >> 5;          // warp id = leaf slice
    const int bbase = blockIdx.x * ROWS;
    const int tbase = blockIdx.y * TGROUP;

    // Stage 64 x-rows as half2 row-pairs. Warp handles 4 row-pairs; per pair,
    // lanes read coalesced float4 from both rows, pack, scatter-STS (4-way
    // bank conflicts, one-time).
    {
        const float4* x4 = reinterpret_cast<const float4*>(x);
#pragma unroll
        for (int rp = 0; rp < 4; rp++) {
            const int l = s * 4 + rp;              // row-pair id = low row
            const float4* rowA = x4 + (size_t)(bbase + l) * 128;
            const float4* rowB = x4 + (size_t)(bbase + l + 32) * 128;
#pragma unroll
            for (int i = 0; i < 4; i++) {
                float4 a = rowA[i * 32 + lane];
                float4 b = rowB[i * 32 + lane];
                const float av[4] = {a.x, a.y, a.z, a.w};
                const float bv[4] = {b.x, b.y, b.z, b.w};
#pragma unroll
                for (int j = 0; j < 4; j++) {
                    int f = (i * 32 + lane) * 4 + j;
                    __half2 h2 = __floats2half2_rn(av[j], bv[j]);
                    xs[(f << 5) | (l ^ (f & 31))] =
                        *reinterpret_cast<unsigned*>(&h2);
                }
            }
        }
    }

    // Warp-constant path node ids / sign splats (levels 0..2); level-3 = 7+s.
    const ull sg0 = (s & 4) ? H2 : NH2;
    const ull sg1 = (s & 2) ? H2 : NH2;
    const ull sg2 = (s & 1) ? H2 : NH2;
    const int a1 = 1 + (s >> 2);
    const int a2 = 3 + (s >> 1);
    const int a3 = 7 + s;

    const __half2 five2 = __floats2half2_rn(5.0f, 5.0f);

    ull accA[4] = {0, 0, 0, 0};
    ull accB[4] = {0, 0, 0, 0};

    // Evaluate one node for the lane's row pair: 1 LDS.32 + HFMA2 + 2 cvt +
    // 2 tanh; result packed {rowA, rowB} in f32x2.
    auto nodeth = [&](unsigned f, unsigned tbbits) -> ull {
        unsigned word = (f << 5) | (lane ^ (f & 31u));
        unsigned xb = xs[word];
        __half2 xv = *reinterpret_cast<__half2*>(&xb);
        __half2 tb = *reinterpret_cast<__half2*>(&tbbits);
        __half2 z2 = __hfma2(xv, five2, tb);
        float2 zf = __half22float2(z2);
        return pk2(tanhf_hw(zf.x), tanhf_hw(zf.y));
    };

    const uint4* nd4 = reinterpret_cast<const uint4*>(nd);

#pragma unroll 1
    for (int tt = 0; tt < TGROUP; tt++) {
        const int t = tbase + tt;
        __syncthreads();   // xs staged / previous tree's tables released

        // Stage node table (255 uint2, slot d+1) + Cw (512 float4).
        {
            const uint2* gsrc = g_node + (size_t)t * DNODES;
            if (tid < DNODES) nd[tid + 1] = gsrc[tid];
            const float4* cws = reinterpret_cast<const float4*>(
                Cw + (size_t)t * (KLEAF * CCLS));
            cw[tid]       = cws[tid];
            cw[tid + 256] = cws[tid + 256];
        }
        __syncthreads();

        // Path levels 0..3 (scalar uint2 broadcasts; slot = node+1).
        uint2 n0 = nd[1], n1 = nd[a1 + 1], n2 = nd[a2 + 1], n3 = nd[a3 + 1];
        ull th0 = nodeth(n0.x, n0.y);
        ull th1 = nodeth(n1.x, n1.y);
        ull th2 = nodeth(n2.x, n2.y);
        ull th3 = nodeth(n3.x, n3.y);
        ull pre = mul2(mul2(ffma2(sg0, th0, H2), ffma2(sg1, th1, H2)),
                       ffma2(sg2, th2, H2));
        ull pA = mul2(pre, ffma2(NH2, th3, H2));
        ull pB = mul2(pre, ffma2(H2,  th3, H2));

        // Level 4: nodes 15+2s,16+2s -> slots 16+2s (uint4 at nd4[8+s]).
        ull q0, q1, q2, q3;
        {
            uint4 v = nd4[8 + s];
            ull ta = nodeth(v.x, v.y);
            ull tb = nodeth(v.z, v.w);
            q0 = mul2(pA, ffma2(NH2, ta, H2)); q1 = mul2(pA, ffma2(H2, ta, H2));
            q2 = mul2(pB, ffma2(NH2, tb, H2)); q3 = mul2(pB, ffma2(H2, tb, H2));
        }
        // Level 5: slots 32+4s -> nd4[16+2s], nd4[17+2s].
        ull r[8];
#pragma unroll
        for (int j = 0; j < 2; j++) {
            uint4 v = nd4[16 + 2 * s + j];
            ull ta = nodeth(v.x, v.y);
            ull tb = nodeth(v.z, v.w);
            ull qa = (j == 0) ? q0 : q2;
            ull qb = (j == 0) ? q1 : q3;
            r[4 * j + 0] = mul2(qa, ffma2(NH2, ta, H2));
            r[4 * j + 1] = mul2(qa, ffma2(H2,  ta, H2));
            r[4 * j + 2] = mul2(qb, ffma2(NH2, tb, H2));
            r[4 * j + 3] = mul2(qb, ffma2(H2,  tb, H2));
        }

        // Levels 6+7 interleaved per level-6 node pair (keeps regs low).
        const ulonglong2* cwp = reinterpret_cast<const ulonglong2*>(cw) + (size_t)s * 64;
#pragma unroll
        for (int j = 0; j < 4; j++) {
            // Level 6 pair: slots 64+8s+2j -> nd4[32+4s+j].
            uint4 v6 = nd4[32 + 4 * s + j];
            ull t6a = nodeth(v6.x, v6.y);
            ull t6b = nodeth(v6.z, v6.w);
            ull u0 = mul2(r[2 * j],     ffma2(NH2, t6a, H2));
            ull u1 = mul2(r[2 * j],     ffma2(H2,  t6a, H2));
            ull u2 = mul2(r[2 * j + 1], ffma2(NH2, t6b, H2));
            ull u3 = mul2(r[2 * j + 1], ffma2(H2,  t6b, H2));

            // Level 7: 4 nodes -> nd4[64+8s+2j], nd4[64+8s+2j+1].
            uint4 v7a = nd4[64 + 8 * s + 2 * j];
            uint4 v7b = nd4[65 + 8 * s + 2 * j];
            ull th7[4];
            th7[0] = nodeth(v7a.x, v7a.y);
            th7[1] = nodeth(v7a.z, v7a.w);
            th7[2] = nodeth(v7b.x, v7b.y);
            th7[3] = nodeth(v7b.z, v7b.w);
            ull uu[4] = {u0, u1, u2, u3};
#pragma unroll
            for (int i = 0; i < 4; i++) {
                const int i7 = 4 * j + i;          // level-7 node within slice
                ull th = th7[i];
                ull P0 = mul2(uu[i], ffma2(NH2, th, H2));
                ull P1 = mul2(uu[i], ffma2(H2,  th, H2));
                float P0A, P0B, P1A, P1B;
                upk2(P0, P0A, P0B);
                upk2(P1, P1A, P1B);
                ulonglong2 cA0 = cwp[4 * i7 + 0];  // leaf 2*i7  : classes 0..3
                ulonglong2 cA1 = cwp[4 * i7 + 1];  // leaf 2*i7  : classes 4..7
                ulonglong2 cB0 = cwp[4 * i7 + 2];  // leaf 2*i7+1: classes 0..3
                ulonglong2 cB1 = cwp[4 * i7 + 3];  // leaf 2*i7+1: classes 4..7
                ull pp0A = pk2(P0A, P0A), pp1A = pk2(P1A, P1A);
                ull pp0B = pk2(P0B, P0B), pp1B = pk2(P1B, P1B);
                accA[0] = ffma2(pp0A, cA0.x, accA[0]);
                accA[1] = ffma2(pp0A, cA0.y, accA[1]);
                accA[2] = ffma2(pp0A, cA1.x, accA[2]);
                accA[3] = ffma2(pp0A, cA1.y, accA[3]);
                accA[0] = ffma2(pp1A, cB0.x, accA[0]);
                accA[1] = ffma2(pp1A, cB0.y, accA[1]);
                accA[2] = ffma2(pp1A, cB1.x, accA[2]);
                accA[3] = ffma2(pp1A, cB1.y, accA[3]);
                accB[0] = ffma2(pp0B, cA0.x, accB[0]);
                accB[1] = ffma2(pp0B, cA0.y, accB[1]);
                accB[2] = ffma2(pp0B, cA1.x, accB[2]);
                accB[3] = ffma2(pp0B, cA1.y, accB[3]);
                accB[0] = ffma2(pp1B, cB0.x, accB[0]);
                accB[1] = ffma2(pp1B, cB0.y, accB[1]);
                accB[2] = ffma2(pp1B, cB1.x, accB[2]);
                accB[3] = ffma2(pp1B, cB1.y, accB[3]);
            }
        }
    }

    // Write out: lane owns rows bbase+lane and bbase+lane+32 for its slice.
    const float inv_t = 1.0f / (float)TREES;
    float aA[CCLS], aB[CCLS];
#pragma unroll
    for (int qq = 0; qq < 4; qq++) {
        upk2(accA[qq], aA[2 * qq], aA[2 * qq + 1]);
        upk2(accB[qq], aB[2 * qq], aB[2 * qq + 1]);
    }
    float* orowA = out + (size_t)(bbase + lane) * CCLS;
    float* orowB = out + (size_t)(bbase + lane + 32) * CCLS;
#pragma unroll
    for (int c = 0; c < CCLS; c++) {
        atomicAdd(&orowA[c], aA[c] * inv_t);
        atomicAdd(&orowB[c], aB[c] * inv_t);
    }
}

// ---------------------------------------------------------------------------
extern "C" void kernel_launch(void* const* d_in, const int* in_sizes, int n_in,
                              void* d_out, int out_size)
{
    // Identify inputs by element count (order per metadata: input, W1, b1,
    // Bpos, Bneg, Cw — Bpos/Bneg are structurally fixed and unused).
    const float* x  = nullptr;
    const float* W1 = nullptr;
    const float* b1 = nullptr;
    const float* Cw = nullptr;
    for (int i = 0; i < n_in; i++) {
        switch (in_sizes[i]) {
            case BATCH * MFEAT:          x  = (const float*)d_in[i]; break; // 2097152
            case TREES * DNODES * MFEAT: W1 = (const float*)d_in[i]; break; // 8355840
            case TREES * DNODES:         b1 = (const float*)d_in[i]; break; // 16320
            case TREES * KLEAF * CCLS:   Cw = (const float*)d_in[i]; break; // 131072
            default: break;                                                 // Bpos/Bneg
        }
    }
    float* out = (float*)d_out;

    // xs (64 KB) + nd (258 uint2) + Cw (512 float4) = 75792 B -> 3 CTAs/SM.
    static const size_t smem_bytes = 512 * 32 * 4 + 258 * 8 + 512 * 16;
    cudaFuncSetAttribute(forest_kernel,
                         cudaFuncAttributeMaxDynamicSharedMemorySize,
                         (int)smem_bytes);

    cudaMemsetAsync(d_out, 0, (size_t)out_size * sizeof(float), 0);

    {
        int rows = TREES * DNODES;
        int warps_per_block = 8;
        int blocks = (rows + warps_per_block - 1) / warps_per_block;
        prep_kernel<<<blocks, warps_per_block * 32>>>(W1, b1);
    }

    dim3 grid(BATCH / ROWS, TREES / TGROUP);   // (64, 16) = 1024 CTAs
    forest_kernel<<<grid, 256, smem_bytes>>>(x, Cw, out);
}

// round 14
// speedup vs baseline: 1.0337x; 1.0337x over previous
#include <cuda_runtime.h>
#include <cuda_fp16.h>
#include <cuda_bf16.h>
#include <cstdint>

// Problem constants (fixed by the dataset).
#define TREES 64
#define DNODES 255      // internal nodes per tree (2^8 - 1)
#define KLEAF 256       // leaves per tree
#define MFEAT 512       // features
#define CCLS 8          // classes
#define BATCH 4096

// Blocking: CTA = 256 threads (8 warps = 8 leaf slices) over 64 batch rows.
// Lane l owns rows (bbase+l, bbase+l+32), packed as half2 in smem.
#define ROWS 64
#define TGROUP 4        // trees per CTA -> grid (64, 16) = 1024 CTAs

// Scratch (no cudaMalloc allowed): packed per-node parameters.
// g_node[t*DNODES+d] = { feature_index, half2{5*b1, 5*b1} }.
__device__ uint2 g_node[TREES * DNODES];

// ---------------------------------------------------------------------------
// Preprocess: extract one-hot feature index from W1 rows; pack with half2(5*b1).
// One warp per (t,d) row of 512 floats.
// ---------------------------------------------------------------------------
__global__ void prep_kernel(const float* __restrict__ W1,
                            const float* __restrict__ b1)
{
    int row = blockIdx.x * (blockDim.x >> 5) + (threadIdx.x >> 5);
    if (row >= TREES * DNODES) return;
    int lane = threadIdx.x & 31;

    const float4* w4 = reinterpret_cast<const float4*>(W1 + (size_t)row * MFEAT);
    int idx = 0;
#pragma unroll
    for (int i = 0; i < 4; i++) {
        float4 v = w4[i * 32 + lane];
        int base = (i * 32 + lane) * 4;
        if (v.x != 0.0f) idx = base + 0;
        if (v.y != 0.0f) idx = base + 1;
        if (v.z != 0.0f) idx = base + 2;
        if (v.w != 0.0f) idx = base + 3;
    }
#pragma unroll
    for (int off = 16; off; off >>= 1)
        idx = max(idx, __shfl_xor_sync(0xffffffffu, idx, off));
    if (lane == 0) {
        // sigmoid(10x+10b) = 0.5 + 0.5*tanh(5x+5b)
        __half   h  = __float2half(5.0f * b1[row]);
        __half2  h2 = __half2half2(h);
        g_node[row] = make_uint2((unsigned)idx,
                                 *reinterpret_cast<unsigned*>(&h2));
    }
}

typedef unsigned long long ull;

__device__ __forceinline__ ull pk2(float lo, float hi)
{
    ull r;
    asm("mov.b64 %0, {%1, %2};" : "=l"(r) : "f"(lo), "f"(hi));
    return r;
}
__device__ __forceinline__ ull ffma2(ull a, ull b, ull c)
{
    ull d;
    asm("fma.rn.f32x2 %0, %1, %2, %3;" : "=l"(d) : "l"(a), "l"(b), "l"(c));
    return d;
}
__device__ __forceinline__ void upk2(ull v, float& lo, float& hi)
{
    asm("mov.b64 {%0, %1}, %2;" : "=f"(lo), "=f"(hi) : "l"(v));
}

// tanh on a half2 pair: single MUFU op (sm_75+).
__device__ __forceinline__ __half2 tanh_h2(__half2 z)
{
    unsigned zi = *reinterpret_cast<unsigned*>(&z);
    unsigned ri;
    asm("tanh.approx.f16x2 %0, %1;" : "=r"(ri) : "r"(zi));
    return *reinterpret_cast<__half2*>(&ri);
}

// ---------------------------------------------------------------------------
// Main kernel. 256 threads (8 warps = 8 slices), 64 rows as 32 half2 row-pairs.
// xs layout: word index (f<<5) | (lane ^ (f&31)) -> per-node gather is ONE
// LDS.32, conflict-free. Node eval is fully fp16: HFMA2 z + tanh.approx.f16x2
// (one MUFU for BOTH rows, no cvts). Tree products in HFMA2/HMUL2; conversion
// to f32 only at the 16 level-7 leaf-prob pairs feeding the f32 contraction.
// Next tree's nd/Cw tables are prefetched into registers during compute.
// ---------------------------------------------------------------------------
__global__ __launch_bounds__(256, 3)
void forest_kernel(const float* __restrict__ x,
                   const float* __restrict__ Cw,
                   float* __restrict__ out)
{
    extern __shared__ unsigned smem_u[];
    unsigned* xs  = smem_u;                                       // 512*32 words (64 KB)
    uint2*    nd  = reinterpret_cast<uint2*>(smem_u + 512 * 32);  // 258 slots (node d -> d+1)
    float4*   cw  = reinterpret_cast<float4*>(smem_u + 512 * 32 + 258 * 2); // 512 float4

    const int tid   = threadIdx.x;
    const int lane  = tid & 31;
    const int s     = tid >> 5;          // warp id = leaf slice
    const int bbase = blockIdx.x * ROWS;
    const int tbase = blockIdx.y * TGROUP;

    // Stage 64 x-rows as half2 row-pairs. Warp handles 4 row-pairs; per pair,
    // lanes read coalesced float4 from both rows, pack, scatter-STS.
    {
        const float4* x4 = reinterpret_cast<const float4*>(x);
#pragma unroll
        for (int rp = 0; rp < 4; rp++) {
            const int l = s * 4 + rp;              // row-pair id = low row
            const float4* rowA = x4 + (size_t)(bbase + l) * 128;
            const float4* rowB = x4 + (size_t)(bbase + l + 32) * 128;
#pragma unroll
            for (int i = 0; i < 4; i++) {
                float4 a = rowA[i * 32 + lane];
                float4 b = rowB[i * 32 + lane];
                const float av[4] = {a.x, a.y, a.z, a.w};
                const float bv[4] = {b.x, b.y, b.z, b.w};
#pragma unroll
                for (int j = 0; j < 4; j++) {
                    int f = (i * 32 + lane) * 4 + j;
                    __half2 h2 = __floats2half2_rn(av[j], bv[j]);
                    xs[(f << 5) | (l ^ (f & 31))] =
                        *reinterpret_cast<unsigned*>(&h2);
                }
            }
        }
    }

    // Warp-constant path ids / half2 sign constants (levels 0..2); lvl3 = 7+s.
    const __half2 h05  = __floats2half2_rn(0.5f, 0.5f);
    const __half2 nh05 = __floats2half2_rn(-0.5f, -0.5f);
    const __half2 sg0h = (s & 4) ? h05 : nh05;
    const __half2 sg1h = (s & 2) ? h05 : nh05;
    const __half2 sg2h = (s & 1) ? h05 : nh05;
    const int a1 = 1 + (s >> 2);
    const int a2 = 3 + (s >> 1);
    const int a3 = 7 + s;

    const __half2 five2 = __floats2half2_rn(5.0f, 5.0f);

    ull accA[4] = {0, 0, 0, 0};
    ull accB[4] = {0, 0, 0, 0};

    // Evaluate one node for the lane's row pair: LDS.32 + HFMA2 + 1 MUFU.
    auto nodeth = [&](unsigned f, unsigned tbbits) -> __half2 {
        unsigned word = (f << 5) | (lane ^ (f & 31u));
        unsigned xb = xs[word];
        __half2 xv = *reinterpret_cast<__half2*>(&xb);
        __half2 tb = *reinterpret_cast<__half2*>(&tbbits);
        return tanh_h2(__hfma2(xv, five2, tb));
    };
    auto facn = [&](__half2 th) -> __half2 { return __hfma2(nh05, th, h05); };
    auto facp = [&](__half2 th) -> __half2 { return __hfma2(h05,  th, h05); };

    const uint4* nd4 = reinterpret_cast<const uint4*>(nd);

    // Register prefetch buffers for the per-tree tables.
    uint2  nreg = make_uint2(0u, 0u);
    float4 c0reg, c1reg;
    auto ldg_tables = [&](int t_idx) {
        const int t = tbase + t_idx;
        if (tid < DNODES) nreg = g_node[(size_t)t * DNODES + tid];
        const float4* cws = reinterpret_cast<const float4*>(
            Cw + (size_t)t * (KLEAF * CCLS));
        c0reg = cws[tid];
        c1reg = cws[tid + 256];
    };

    ldg_tables(0);

#pragma unroll 1
    for (int tt = 0; tt < TGROUP; tt++) {
        __syncthreads();   // xs staged / previous tree's table reads done

        // Commit prefetched tables to smem; start next tree's LDG.
        if (tid < DNODES) nd[tid + 1] = nreg;
        cw[tid]       = c0reg;
        cw[tid + 256] = c1reg;
        if (tt + 1 < TGROUP) ldg_tables(tt + 1);
        __syncthreads();

        // Path levels 0..3 (scalar uint2 broadcasts; slot = node+1).
        uint2 n0 = nd[1], n1 = nd[a1 + 1], n2 = nd[a2 + 1], n3 = nd[a3 + 1];
        __half2 th0 = nodeth(n0.x, n0.y);
        __half2 th1 = nodeth(n1.x, n1.y);
        __half2 th2 = nodeth(n2.x, n2.y);
        __half2 th3 = nodeth(n3.x, n3.y);
        __half2 pre = __hmul2(__hmul2(__hfma2(sg0h, th0, h05),
                                      __hfma2(sg1h, th1, h05)),
                              __hfma2(sg2h, th2, h05));
        __half2 pA = __hmul2(pre, facn(th3));
        __half2 pB = __hmul2(pre, facp(th3));

        // Level 4: nodes 15+2s,16+2s -> slots 16+2s (uint4 at nd4[8+s]).
        __half2 q0, q1, q2, q3;
        {
            uint4 v = nd4[8 + s];
            __half2 ta = nodeth(v.x, v.y);
            __half2 tb = nodeth(v.z, v.w);
            q0 = __hmul2(pA, facn(ta)); q1 = __hmul2(pA, facp(ta));
            q2 = __hmul2(pB, facn(tb)); q3 = __hmul2(pB, facp(tb));
        }
        // Level 5: slots 32+4s -> nd4[16+2s], nd4[17+2s].
        __half2 r[8];
#pragma unroll
        for (int j = 0; j < 2; j++) {
            uint4 v = nd4[16 + 2 * s + j];
            __half2 ta = nodeth(v.x, v.y);
            __half2 tb = nodeth(v.z, v.w);
            __half2 qa = (j == 0) ? q0 : q2;
            __half2 qb = (j == 0) ? q1 : q3;
            r[4 * j + 0] = __hmul2(qa, facn(ta));
            r[4 * j + 1] = __hmul2(qa, facp(ta));
            r[4 * j + 2] = __hmul2(qb, facn(tb));
            r[4 * j + 3] = __hmul2(qb, facp(tb));
        }

        // Levels 6+7 interleaved per level-6 node pair (keeps regs low).
        const ulonglong2* cwp = reinterpret_cast<const ulonglong2*>(cw) + (size_t)s * 64;
#pragma unroll
        for (int j = 0; j < 4; j++) {
            // Level 6 pair: slots 64+8s+2j -> nd4[32+4s+j].
            uint4 v6 = nd4[32 + 4 * s + j];
            __half2 t6a = nodeth(v6.x, v6.y);
            __half2 t6b = nodeth(v6.z, v6.w);
            __half2 uu[4];
            uu[0] = __hmul2(r[2 * j],     facn(t6a));
            uu[1] = __hmul2(r[2 * j],     facp(t6a));
            uu[2] = __hmul2(r[2 * j + 1], facn(t6b));
            uu[3] = __hmul2(r[2 * j + 1], facp(t6b));

            // Level 7: 4 nodes -> nd4[64+8s+2j], nd4[64+8s+2j+1].
            uint4 v7a = nd4[64 + 8 * s + 2 * j];
            uint4 v7b = nd4[65 + 8 * s + 2 * j];
            __half2 th7[4];
            th7[0] = nodeth(v7a.x, v7a.y);
            th7[1] = nodeth(v7a.z, v7a.w);
            th7[2] = nodeth(v7b.x, v7b.y);
            th7[3] = nodeth(v7b.z, v7b.w);
#pragma unroll
            for (int i = 0; i < 4; i++) {
                const int i7 = 4 * j + i;          // level-7 node within slice
                __half2 P0 = __hmul2(uu[i], facn(th7[i]));
                __half2 P1 = __hmul2(uu[i], facp(th7[i]));
                float P0A = __low2float(P0), P0B = __high2float(P0);
                float P1A = __low2float(P1), P1B = __high2float(P1);
                ulonglong2 cA0 = cwp[4 * i7 + 0];  // leaf 2*i7  : classes 0..3
                ulonglong2 cA1 = cwp[4 * i7 + 1];  // leaf 2*i7  : classes 4..7
                ulonglong2 cB0 = cwp[4 * i7 + 2];  // leaf 2*i7+1: classes 0..3
                ulonglong2 cB1 = cwp[4 * i7 + 3];  // leaf 2*i7+1: classes 4..7
                ull pp0A = pk2(P0A, P0A), pp1A = pk2(P1A, P1A);
                ull pp0B = pk2(P0B, P0B), pp1B = pk2(P1B, P1B);
                accA[0] = ffma2(pp0A, cA0.x, accA[0]);
                accA[1] = ffma2(pp0A, cA0.y, accA[1]);
                accA[2] = ffma2(pp0A, cA1.x, accA[2]);
                accA[3] = ffma2(pp0A, cA1.y, accA[3]);
                accA[0] = ffma2(pp1A, cB0.x, accA[0]);
                accA[1] = ffma2(pp1A, cB0.y, accA[1]);
                accA[2] = ffma2(pp1A, cB1.x, accA[2]);
                accA[3] = ffma2(pp1A, cB1.y, accA[3]);
                accB[0] = ffma2(pp0B, cA0.x, accB[0]);
                accB[1] = ffma2(pp0B, cA0.y, accB[1]);
                accB[2] = ffma2(pp0B, cA1.x, accB[2]);
                accB[3] = ffma2(pp0B, cA1.y, accB[3]);
                accB[0] = ffma2(pp1B, cB0.x, accB[0]);
                accB[1] = ffma2(pp1B, cB0.y, accB[1]);
                accB[2] = ffma2(pp1B, cB1.x, accB[2]);
                accB[3] = ffma2(pp1B, cB1.y, accB[3]);
            }
        }
    }

    // Write out: lane owns rows bbase+lane and bbase+lane+32 for its slice.
    const float inv_t = 1.0f / (float)TREES;
    float aA[CCLS], aB[CCLS];
#pragma unroll
    for (int qq = 0; qq < 4; qq++) {
        upk2(accA[qq], aA[2 * qq], aA[2 * qq + 1]);
        upk2(accB[qq], aB[2 * qq], aB[2 * qq + 1]);
    }
    float* orowA = out + (size_t)(bbase + lane) * CCLS;
    float* orowB = out + (size_t)(bbase + lane + 32) * CCLS;
#pragma unroll
    for (int c = 0; c < CCLS; c++) {
        atomicAdd(&orowA[c], aA[c] * inv_t);
        atomicAdd(&orowB[c], aB[c] * inv_t);
    }
}

// ---------------------------------------------------------------------------
extern "C" void kernel_launch(void* const* d_in, const int* in_sizes, int n_in,
                              void* d_out, int out_size)
{
    // Identify inputs by element count (order per metadata: input, W1, b1,
    // Bpos, Bneg, Cw — Bpos/Bneg are structurally fixed and unused).
    const float* x  = nullptr;
    const float* W1 = nullptr;
    const float* b1 = nullptr;
    const float* Cw = nullptr;
    for (int i = 0; i < n_in; i++) {
        switch (in_sizes[i]) {
            case BATCH * MFEAT:          x  = (const float*)d_in[i]; break; // 2097152
            case TREES * DNODES * MFEAT: W1 = (const float*)d_in[i]; break; // 8355840
            case TREES * DNODES:         b1 = (const float*)d_in[i]; break; // 16320
            case TREES * KLEAF * CCLS:   Cw = (const float*)d_in[i]; break; // 131072
            default: break;                                                 // Bpos/Bneg
        }
    }
    float* out = (float*)d_out;

    // xs (64 KB) + nd (258 uint2) + Cw (512 float4) = 75792 B -> 3 CTAs/SM.
    static const size_t smem_bytes = 512 * 32 * 4 + 258 * 8 + 512 * 16;
    cudaFuncSetAttribute(forest_kernel,
                         cudaFuncAttributeMaxDynamicSharedMemorySize,
                         (int)smem_bytes);

    cudaMemsetAsync(d_out, 0, (size_t)out_size * sizeof(float), 0);

    {
        int rows = TREES * DNODES;
        int warps_per_block = 8;
        int blocks = (rows + warps_per_block - 1) / warps_per_block;
        prep_kernel<<<blocks, warps_per_block * 32>>>(W1, b1);
    }

    dim3 grid(BATCH / ROWS, TREES / TGROUP);   // (64, 16) = 1024 CTAs
    forest_kernel<<<grid, 256, smem_bytes>>>(x, Cw, out);
}

// round 15
// speedup vs baseline: 1.0649x; 1.0302x over previous
#include <cuda_runtime.h>
#include <cuda_fp16.h>
#include <cuda_bf16.h>
#include <cstdint>

// Problem constants (fixed by the dataset).
#define TREES 64
#define DNODES 255      // internal nodes per tree (2^8 - 1)
#define KLEAF 256       // leaves per tree
#define MFEAT 512       // features
#define CCLS 8          // classes
#define BATCH 4096

// Blocking: CTA = 256 threads (8 warps = 8 leaf slices) over 64 batch rows.
// Lane l owns rows (bbase+l, bbase+l+32), packed as half2 in smem.
#define ROWS 64
#define TGROUP 4        // trees per CTA -> grid (64, 16) = 1024 CTAs

// xs word index: (f<<5) | (l ^ ((f>>2)&31)).
//  - gather (fixed f, varying l): bank = l ^ c -> conflict-free
//  - staging (fixed l, lane k handles f=(i*32+k)*4+j): (f>>2)&31 = k ->
//    bank = l ^ k -> conflict-free STS as well.
__device__ __forceinline__ unsigned xword(unsigned f, unsigned l)
{
    return (f << 5) | (l ^ ((f >> 2) & 31u));
}

// Scratch (no cudaMalloc allowed): packed per-node parameters.
// g_node[t*DNODES+d] = { feature_index, half2{5*b1, 5*b1} }.
__device__ uint2 g_node[TREES * DNODES];

// ---------------------------------------------------------------------------
// Preprocess: extract one-hot feature index from W1 rows; pack with half2(5*b1).
// One warp per (t,d) row of 512 floats.
// ---------------------------------------------------------------------------
__global__ void prep_kernel(const float* __restrict__ W1,
                            const float* __restrict__ b1)
{
    int row = blockIdx.x * (blockDim.x >> 5) + (threadIdx.x >> 5);
    if (row >= TREES * DNODES) return;
    int lane = threadIdx.x & 31;

    const float4* w4 = reinterpret_cast<const float4*>(W1 + (size_t)row * MFEAT);
    int idx = 0;
#pragma unroll
    for (int i = 0; i < 4; i++) {
        float4 v = w4[i * 32 + lane];
        int base = (i * 32 + lane) * 4;
        if (v.x != 0.0f) idx = base + 0;
        if (v.y != 0.0f) idx = base + 1;
        if (v.z != 0.0f) idx = base + 2;
        if (v.w != 0.0f) idx = base + 3;
    }
#pragma unroll
    for (int off = 16; off; off >>= 1)
        idx = max(idx, __shfl_xor_sync(0xffffffffu, idx, off));
    if (lane == 0) {
        // sigmoid(10x+10b) = 0.5 + 0.5*tanh(5x+5b)
        __half   h  = __float2half(5.0f * b1[row]);
        __half2  h2 = __half2half2(h);
        g_node[row] = make_uint2((unsigned)idx,
                                 *reinterpret_cast<unsigned*>(&h2));
    }
}

// th = tanh(z) via single MUFU.TANH (f32 — precision headroom).
__device__ __forceinline__ float tanhf_hw(float z)
{
    float r;
    asm("tanh.approx.f32 %0, %1;" : "=f"(r) : "f"(z));
    return r;
}

typedef unsigned long long ull;

__device__ __forceinline__ ull pk2(float lo, float hi)
{
    ull r;
    asm("mov.b64 %0, {%1, %2};" : "=l"(r) : "f"(lo), "f"(hi));
    return r;
}
__device__ __forceinline__ ull ffma2(ull a, ull b, ull c)
{
    ull d;
    asm("fma.rn.f32x2 %0, %1, %2, %3;" : "=l"(d) : "l"(a), "l"(b), "l"(c));
    return d;
}
__device__ __forceinline__ ull mul2(ull a, ull b)
{
    ull d;
    asm("mul.rn.f32x2 %0, %1, %2;" : "=l"(d) : "l"(a), "l"(b));
    return d;
}
__device__ __forceinline__ void upk2(ull v, float& lo, float& hi)
{
    asm("mov.b64 {%0, %1}, %2;" : "=f"(lo), "=f"(hi) : "l"(v));
}

#define H2  0x3F0000003F000000ull   // {0.5f, 0.5f}
#define NH2 0xBF000000BF000000ull   // {-0.5f, -0.5f}

// ---------------------------------------------------------------------------
// Main kernel. 256 threads (8 warps = 8 slices), 64 rows as 32 half2 row-pairs
// in a fully conflict-free smem layout (gather AND staging). Node eval:
// LDS.32 + HFMA2 + 2 cvt + 2 f32 tanh, packed f32x2 products, f32 contraction
// with Cw from smem. Next tree's nd/Cw tables prefetched into registers
// during compute (hides staging L2 latency).
// ---------------------------------------------------------------------------
__global__ __launch_bounds__(256, 3)
void forest_kernel(const float* __restrict__ x,
                   const float* __restrict__ Cw,
                   float* __restrict__ out)
{
    extern __shared__ unsigned smem_u[];
    unsigned* xs  = smem_u;                                       // 512*32 words (64 KB)
    uint2*    nd  = reinterpret_cast<uint2*>(smem_u + 512 * 32);  // 258 slots (node d -> d+1)
    float4*   cw  = reinterpret_cast<float4*>(smem_u + 512 * 32 + 258 * 2); // 512 float4

    const int tid   = threadIdx.x;
    const int lane  = tid & 31;
    const int s     = tid >> 5;          // warp id = leaf slice
    const int bbase = blockIdx.x * ROWS;
    const int tbase = blockIdx.y * TGROUP;

    // Stage 64 x-rows as half2 row-pairs (conflict-free STS via xword).
    {
        const float4* x4 = reinterpret_cast<const float4*>(x);
#pragma unroll
        for (int rp = 0; rp < 4; rp++) {
            const int l = s * 4 + rp;              // row-pair id = low row
            const float4* rowA = x4 + (size_t)(bbase + l) * 128;
            const float4* rowB = x4 + (size_t)(bbase + l + 32) * 128;
#pragma unroll
            for (int i = 0; i < 4; i++) {
                float4 a = rowA[i * 32 + lane];
                float4 b = rowB[i * 32 + lane];
                const float av[4] = {a.x, a.y, a.z, a.w};
                const float bv[4] = {b.x, b.y, b.z, b.w};
#pragma unroll
                for (int j = 0; j < 4; j++) {
                    unsigned f = (unsigned)((i * 32 + lane) * 4 + j);
                    __half2 h2 = __floats2half2_rn(av[j], bv[j]);
                    xs[xword(f, (unsigned)l)] = *reinterpret_cast<unsigned*>(&h2);
                }
            }
        }
    }

    // Warp-constant path ids / sign splats (levels 0..2); level-3 = 7+s.
    const ull sg0 = (s & 4) ? H2 : NH2;
    const ull sg1 = (s & 2) ? H2 : NH2;
    const ull sg2 = (s & 1) ? H2 : NH2;
    const int a1 = 1 + (s >> 2);
    const int a2 = 3 + (s >> 1);
    const int a3 = 7 + s;

    const __half2 five2 = __floats2half2_rn(5.0f, 5.0f);

    ull accA[4] = {0, 0, 0, 0};
    ull accB[4] = {0, 0, 0, 0};

    // Evaluate one node for the lane's row pair: LDS.32 + HFMA2 + 2 cvt +
    // 2 f32 tanh; result packed {rowA, rowB} as f32x2.
    auto nodeth = [&](unsigned f, unsigned tbbits) -> ull {
        unsigned xb = xs[xword(f, (unsigned)lane)];
        __half2 xv = *reinterpret_cast<__half2*>(&xb);
        __half2 tb = *reinterpret_cast<__half2*>(&tbbits);
        __half2 z2 = __hfma2(xv, five2, tb);
        float2 zf = __half22float2(z2);
        return pk2(tanhf_hw(zf.x), tanhf_hw(zf.y));
    };
    auto facn = [&](ull th) -> ull { return ffma2(NH2, th, H2); };
    auto facp = [&](ull th) -> ull { return ffma2(H2,  th, H2); };

    const uint4* nd4 = reinterpret_cast<const uint4*>(nd);

    // Register prefetch buffers for the per-tree tables.
    uint2  nreg = make_uint2(0u, 0u);
    float4 c0reg, c1reg;
    auto ldg_tables = [&](int t_idx) {
        const int t = tbase + t_idx;
        if (tid < DNODES) nreg = g_node[(size_t)t * DNODES + tid];
        const float4* cws = reinterpret_cast<const float4*>(
            Cw + (size_t)t * (KLEAF * CCLS));
        c0reg = cws[tid];
        c1reg = cws[tid + 256];
    };

    ldg_tables(0);

#pragma unroll 1
    for (int tt = 0; tt < TGROUP; tt++) {
        __syncthreads();   // xs staged / previous tree's table reads done

        // Commit prefetched tables to smem; start next tree's LDG.
        if (tid < DNODES) nd[tid + 1] = nreg;
        cw[tid]       = c0reg;
        cw[tid + 256] = c1reg;
        if (tt + 1 < TGROUP) ldg_tables(tt + 1);
        __syncthreads();

        // Path levels 0..3 (scalar uint2 broadcasts; slot = node+1).
        uint2 n0 = nd[1], n1 = nd[a1 + 1], n2 = nd[a2 + 1], n3 = nd[a3 + 1];
        ull th0 = nodeth(n0.x, n0.y);
        ull th1 = nodeth(n1.x, n1.y);
        ull th2 = nodeth(n2.x, n2.y);
        ull th3 = nodeth(n3.x, n3.y);
        ull pre = mul2(mul2(ffma2(sg0, th0, H2), ffma2(sg1, th1, H2)),
                       ffma2(sg2, th2, H2));
        ull pA = mul2(pre, facn(th3));
        ull pB = mul2(pre, facp(th3));

        // Level 4: nodes 15+2s,16+2s -> slots 16+2s (uint4 at nd4[8+s]).
        ull q0, q1, q2, q3;
        {
            uint4 v = nd4[8 + s];
            ull ta = nodeth(v.x, v.y);
            ull tb = nodeth(v.z, v.w);
            q0 = mul2(pA, facn(ta)); q1 = mul2(pA, facp(ta));
            q2 = mul2(pB, facn(tb)); q3 = mul2(pB, facp(tb));
        }
        // Level 5: slots 32+4s -> nd4[16+2s], nd4[17+2s].
        ull r[8];
#pragma unroll
        for (int j = 0; j < 2; j++) {
            uint4 v = nd4[16 + 2 * s + j];
            ull ta = nodeth(v.x, v.y);
            ull tb = nodeth(v.z, v.w);
            ull qa = (j == 0) ? q0 : q2;
            ull qb = (j == 0) ? q1 : q3;
            r[4 * j + 0] = mul2(qa, facn(ta));
            r[4 * j + 1] = mul2(qa, facp(ta));
            r[4 * j + 2] = mul2(qb, facn(tb));
            r[4 * j + 3] = mul2(qb, facp(tb));
        }

        // Levels 6+7 interleaved per level-6 node pair (keeps regs low).
        const ulonglong2* cwp = reinterpret_cast<const ulonglong2*>(cw) + (size_t)s * 64;
#pragma unroll
        for (int j = 0; j < 4; j++) {
            // Level 6 pair: slots 64+8s+2j -> nd4[32+4s+j].
            uint4 v6 = nd4[32 + 4 * s + j];
            ull t6a = nodeth(v6.x, v6.y);
            ull t6b = nodeth(v6.z, v6.w);
            ull uu[4];
            uu[0] = mul2(r[2 * j],     facn(t6a));
            uu[1] = mul2(r[2 * j],     facp(t6a));
            uu[2] = mul2(r[2 * j + 1], facn(t6b));
            uu[3] = mul2(r[2 * j + 1], facp(t6b));

            // Level 7: 4 nodes -> nd4[64+8s+2j], nd4[64+8s+2j+1].
            uint4 v7a = nd4[64 + 8 * s + 2 * j];
            uint4 v7b = nd4[65 + 8 * s + 2 * j];
            ull th7[4];
            th7[0] = nodeth(v7a.x, v7a.y);
            th7[1] = nodeth(v7a.z, v7a.w);
            th7[2] = nodeth(v7b.x, v7b.y);
            th7[3] = nodeth(v7b.z, v7b.w);
#pragma unroll
            for (int i = 0; i < 4; i++) {
                const int i7 = 4 * j + i;          // level-7 node within slice
                ull th = th7[i];
                ull P0 = mul2(uu[i], facn(th));
                ull P1 = mul2(uu[i], facp(th));
                float P0A, P0B, P1A, P1B;
                upk2(P0, P0A, P0B);
                upk2(P1, P1A, P1B);
                ulonglong2 cA0 = cwp[4 * i7 + 0];  // leaf 2*i7  : classes 0..3
                ulonglong2 cA1 = cwp[4 * i7 + 1];  // leaf 2*i7  : classes 4..7
                ulonglong2 cB0 = cwp[4 * i7 + 2];  // leaf 2*i7+1: classes 0..3
                ulonglong2 cB1 = cwp[4 * i7 + 3];  // leaf 2*i7+1: classes 4..7
                ull pp0A = pk2(P0A, P0A), pp1A = pk2(P1A, P1A);
                ull pp0B = pk2(P0B, P0B), pp1B = pk2(P1B, P1B);
                accA[0] = ffma2(pp0A, cA0.x, accA[0]);
                accA[1] = ffma2(pp0A, cA0.y, accA[1]);
                accA[2] = ffma2(pp0A, cA1.x, accA[2]);
                accA[3] = ffma2(pp0A, cA1.y, accA[3]);
                accA[0] = ffma2(pp1A, cB0.x, accA[0]);
                accA[1] = ffma2(pp1A, cB0.y, accA[1]);
                accA[2] = ffma2(pp1A, cB1.x, accA[2]);
                accA[3] = ffma2(pp1A, cB1.y, accA[3]);
                accB[0] = ffma2(pp0B, cA0.x, accB[0]);
                accB[1] = ffma2(pp0B, cA0.y, accB[1]);
                accB[2] = ffma2(pp0B, cA1.x, accB[2]);
                accB[3] = ffma2(pp0B, cA1.y, accB[3]);
                accB[0] = ffma2(pp1B, cB0.x, accB[0]);
                accB[1] = ffma2(pp1B, cB0.y, accB[1]);
                accB[2] = ffma2(pp1B, cB1.x, accB[2]);
                accB[3] = ffma2(pp1B, cB1.y, accB[3]);
            }
        }
    }

    // Write out: lane owns rows bbase+lane and bbase+lane+32 for its slice.
    const float inv_t = 1.0f / (float)TREES;
    float aA[CCLS], aB[CCLS];
#pragma unroll
    for (int qq = 0; qq < 4; qq++) {
        upk2(accA[qq], aA[2 * qq], aA[2 * qq + 1]);
        upk2(accB[qq], aB[2 * qq], aB[2 * qq + 1]);
    }
    float* orowA = out + (size_t)(bbase + lane) * CCLS;
    float* orowB = out + (size_t)(bbase + lane + 32) * CCLS;
#pragma unroll
    for (int c = 0; c < CCLS; c++) {
        atomicAdd(&orowA[c], aA[c] * inv_t);
        atomicAdd(&orowB[c], aB[c] * inv_t);
    }
}

// ---------------------------------------------------------------------------
extern "C" void kernel_launch(void* const* d_in, const int* in_sizes, int n_in,
                              void* d_out, int out_size)
{
    // Identify inputs by element count (order per metadata: input, W1, b1,
    // Bpos, Bneg, Cw — Bpos/Bneg are structurally fixed and unused).
    const float* x  = nullptr;
    const float* W1 = nullptr;
    const float* b1 = nullptr;
    const float* Cw = nullptr;
    for (int i = 0; i < n_in; i++) {
        switch (in_sizes[i]) {
            case BATCH * MFEAT:          x  = (const float*)d_in[i]; break; // 2097152
            case TREES * DNODES * MFEAT: W1 = (const float*)d_in[i]; break; // 8355840
            case TREES * DNODES:         b1 = (const float*)d_in[i]; break; // 16320
            case TREES * KLEAF * CCLS:   Cw = (const float*)d_in[i]; break; // 131072
            default: break;                                                 // Bpos/Bneg
        }
    }
    float* out = (float*)d_out;

    // xs (64 KB) + nd (258 uint2) + Cw (512 float4) = 75792 B -> 3 CTAs/SM.
    static const size_t smem_bytes = 512 * 32 * 4 + 258 * 8 + 512 * 16;
    cudaFuncSetAttribute(forest_kernel,
                         cudaFuncAttributeMaxDynamicSharedMemorySize,
                         (int)smem_bytes);

    cudaMemsetAsync(d_out, 0, (size_t)out_size * sizeof(float), 0);

    {
        int rows = TREES * DNODES;
        int warps_per_block = 8;
        int blocks = (rows + warps_per_block - 1) / warps_per_block;
        prep_kernel<<<blocks, warps_per_block * 32>>>(W1, b1);
    }

    dim3 grid(BATCH / ROWS, TREES / TGROUP);   // (64, 16) = 1024 CTAs
    forest_kernel<<<grid, 256, smem_bytes>>>(x, Cw, out);
}

// round 16
// speedup vs baseline: 1.1299x; 1.0611x over previous
#include <cuda_runtime.h>
#include <cuda_fp16.h>
#include <cuda_bf16.h>
#include <cstdint>

// Problem constants (fixed by the dataset).
#define TREES 64
#define DNODES 255      // internal nodes per tree (2^8 - 1)
#define KLEAF 256       // leaves per tree
#define MFEAT 512       // features
#define CCLS 8          // classes
#define BATCH 4096

// Blocking: CTA = 256 threads (8 warps = 8 leaf slices) over 64 batch rows.
// Lane l owns rows (bbase+l, bbase+l+32), packed as half2 in smem.
#define ROWS 64
#define TGROUP 4        // trees per CTA -> grid (64, 16) = 1024 CTAs

// xs word index: (f<<5) | (l ^ ((f>>2)&31)).
//  - gather (fixed f, varying l): bank = l ^ c -> conflict-free
//  - staging (fixed l, lane k handles f=(i*32+k)*4+j): (f>>2)&31 = k ->
//    bank = l ^ k -> conflict-free STS as well.
__device__ __forceinline__ unsigned xword(unsigned f, unsigned l)
{
    return (f << 5) | (l ^ ((f >> 2) & 31u));
}

// Scratch (no cudaMalloc allowed).
// g_node[t*DNODES+d] = { precomputed-gather-byte-offset, half2{5*b1, 5*b1} }.
//   pre4 = (((f<<5) | ((f>>2)&31)) << 2); gather offset = pre4 ^ (lane<<2).
__device__ uint2 g_node[TREES * DNODES];
// g_cwsd: Cw transformed to leaf-pair (S, D) form:
//   for leaf pair (2*i7, 2*i7+1):  S_c = (cA_c + cB_c)/2,  D_c = (cB_c - cA_c)/2
//   layout [t][i7*16 + c] = S_c, [t][i7*16 + 8 + c] = D_c  (2048 floats/tree).
__device__ float g_cwsd[TREES * KLEAF * CCLS];

// ---------------------------------------------------------------------------
// Preprocess 1: extract one-hot feature index from W1 rows; pack the
// pre-shifted swizzled address constant with half2(5*b1). One warp per row.
// ---------------------------------------------------------------------------
__global__ void prep_kernel(const float* __restrict__ W1,
                            const float* __restrict__ b1)
{
    int row = blockIdx.x * (blockDim.x >> 5) + (threadIdx.x >> 5);
    if (row >= TREES * DNODES) return;
    int lane = threadIdx.x & 31;

    const float4* w4 = reinterpret_cast<const float4*>(W1 + (size_t)row * MFEAT);
    int idx = 0;
#pragma unroll
    for (int i = 0; i < 4; i++) {
        float4 v = w4[i * 32 + lane];
        int base = (i * 32 + lane) * 4;
        if (v.x != 0.0f) idx = base + 0;
        if (v.y != 0.0f) idx = base + 1;
        if (v.z != 0.0f) idx = base + 2;
        if (v.w != 0.0f) idx = base + 3;
    }
#pragma unroll
    for (int off = 16; off; off >>= 1)
        idx = max(idx, __shfl_xor_sync(0xffffffffu, idx, off));
    if (lane == 0) {
        // sigmoid(10x+10b) = 0.5 + 0.5*tanh(5x+5b)
        __half   h  = __float2half(5.0f * b1[row]);
        __half2  h2 = __half2half2(h);
        unsigned f  = (unsigned)idx;
        unsigned pre4 = ((f << 5) | ((f >> 2) & 31u)) << 2;
        g_node[row] = make_uint2(pre4, *reinterpret_cast<unsigned*>(&h2));
    }
}

// ---------------------------------------------------------------------------
// Preprocess 2: Cw -> (S, D) leaf-pair form.
// ---------------------------------------------------------------------------
__global__ void cwprep_kernel(const float* __restrict__ Cw)
{
    int i = blockIdx.x * 256 + threadIdx.x;      // (t, i7, c)
    if (i >= TREES * (KLEAF / 2) * CCLS) return;
    int c  = i & 7;
    int i7 = (i >> 3) & 127;
    int t  = i >> 10;
    const float* base = Cw + (size_t)t * (KLEAF * CCLS);
    float a = base[(2 * i7) * CCLS + c];         // leaf 2*i7
    float b = base[(2 * i7 + 1) * CCLS + c];     // leaf 2*i7+1
    float* dst = g_cwsd + (size_t)t * (KLEAF * CCLS) + i7 * 16;
    dst[c]     = 0.5f * (a + b);                 // S
    dst[8 + c] = 0.5f * (b - a);                 // D
}

// th = tanh(z) via single MUFU.TANH (f32 — precision headroom).
__device__ __forceinline__ float tanhf_hw(float z)
{
    float r;
    asm("tanh.approx.f32 %0, %1;" : "=f"(r) : "f"(z));
    return r;
}

typedef unsigned long long ull;

__device__ __forceinline__ ull pk2(float lo, float hi)
{
    ull r;
    asm("mov.b64 %0, {%1, %2};" : "=l"(r) : "f"(lo), "f"(hi));
    return r;
}
__device__ __forceinline__ ull ffma2(ull a, ull b, ull c)
{
    ull d;
    asm("fma.rn.f32x2 %0, %1, %2, %3;" : "=l"(d) : "l"(a), "l"(b), "l"(c));
    return d;
}
__device__ __forceinline__ ull mul2(ull a, ull b)
{
    ull d;
    asm("mul.rn.f32x2 %0, %1, %2;" : "=l"(d) : "l"(a), "l"(b));
    return d;
}
__device__ __forceinline__ void upk2(ull v, float& lo, float& hi)
{
    asm("mov.b64 {%0, %1}, %2;" : "=f"(lo), "=f"(hi) : "l"(v));
}

#define H2  0x3F0000003F000000ull   // {0.5f, 0.5f}
#define NH2 0xBF000000BF000000ull   // {-0.5f, -0.5f}

// ---------------------------------------------------------------------------
// Main kernel. 256 threads (8 warps = 8 slices), 64 rows as 32 half2 row-pairs
// in a fully conflict-free smem layout (gather AND staging). Node eval:
// 1 XOR (precomputed swizzled address) + LDS.32 + HFMA2 + 2 cvt + 2 f32 tanh.
// Leaf contraction in (S,D) form: leafpair contribution = u*S + (u*th)*D,
// eliminating the per-leaf 0.5±0.5th factors and P products. Next tree's
// nd/cwsd tables prefetched into registers during compute.
// ---------------------------------------------------------------------------
__global__ __launch_bounds__(256, 3)
void forest_kernel(const float* __restrict__ x,
                   float* __restrict__ out)
{
    extern __shared__ unsigned smem_u[];
    unsigned* xs  = smem_u;                                       // 512*32 words (64 KB)
    uint2*    nd  = reinterpret_cast<uint2*>(smem_u + 512 * 32);  // 258 slots (node d -> d+1)
    float4*   cw  = reinterpret_cast<float4*>(smem_u + 512 * 32 + 258 * 2); // 512 float4

    const int tid   = threadIdx.x;
    const int lane  = tid & 31;
    const int s     = tid >> 5;          // warp id = leaf slice
    const int bbase = blockIdx.x * ROWS;
    const int tbase = blockIdx.y * TGROUP;
    const unsigned lane4 = (unsigned)lane << 2;

    // Stage 64 x-rows as half2 row-pairs (conflict-free STS via xword).
    {
        const float4* x4 = reinterpret_cast<const float4*>(x);
#pragma unroll
        for (int rp = 0; rp < 4; rp++) {
            const int l = s * 4 + rp;              // row-pair id = low row
            const float4* rowA = x4 + (size_t)(bbase + l) * 128;
            const float4* rowB = x4 + (size_t)(bbase + l + 32) * 128;
#pragma unroll
            for (int i = 0; i < 4; i++) {
                float4 a = rowA[i * 32 + lane];
                float4 b = rowB[i * 32 + lane];
                const float av[4] = {a.x, a.y, a.z, a.w};
                const float bv[4] = {b.x, b.y, b.z, b.w};
#pragma unroll
                for (int j = 0; j < 4; j++) {
                    unsigned f = (unsigned)((i * 32 + lane) * 4 + j);
                    __half2 h2 = __floats2half2_rn(av[j], bv[j]);
                    xs[xword(f, (unsigned)l)] = *reinterpret_cast<unsigned*>(&h2);
                }
            }
        }
    }

    // Warp-constant path ids / sign splats (levels 0..2); level-3 = 7+s.
    const ull sg0 = (s & 4) ? H2 : NH2;
    const ull sg1 = (s & 2) ? H2 : NH2;
    const ull sg2 = (s & 1) ? H2 : NH2;
    const int a1 = 1 + (s >> 2);
    const int a2 = 3 + (s >> 1);
    const int a3 = 7 + s;

    const __half2 five2 = __floats2half2_rn(5.0f, 5.0f);

    ull accA[4] = {0, 0, 0, 0};
    ull accB[4] = {0, 0, 0, 0};

    // Evaluate one node for the lane's row pair: XOR + LDS.32 + HFMA2 +
    // 2 cvt + 2 f32 tanh; result packed {rowA, rowB} as f32x2.
    auto nodeth = [&](unsigned pre4, unsigned tbbits) -> ull {
        unsigned xb = *reinterpret_cast<const unsigned*>(
            reinterpret_cast<const char*>(xs) + (pre4 ^ lane4));
        __half2 xv = *reinterpret_cast<__half2*>(&xb);
        __half2 tb = *reinterpret_cast<__half2*>(&tbbits);
        __half2 z2 = __hfma2(xv, five2, tb);
        float2 zf = __half22float2(z2);
        return pk2(tanhf_hw(zf.x), tanhf_hw(zf.y));
    };
    auto facn = [&](ull th) -> ull { return ffma2(NH2, th, H2); };
    auto facp = [&](ull th) -> ull { return ffma2(H2,  th, H2); };

    const uint4* nd4 = reinterpret_cast<const uint4*>(nd);

    // Register prefetch buffers for the per-tree tables.
    uint2  nreg = make_uint2(0u, 0u);
    float4 c0reg, c1reg;
    auto ldg_tables = [&](int t_idx) {
        const int t = tbase + t_idx;
        if (tid < DNODES) nreg = g_node[(size_t)t * DNODES + tid];
        const float4* cws = reinterpret_cast<const float4*>(
            g_cwsd + (size_t)t * (KLEAF * CCLS));
        c0reg = cws[tid];
        c1reg = cws[tid + 256];
    };

    ldg_tables(0);

#pragma unroll 1
    for (int tt = 0; tt < TGROUP; tt++) {
        __syncthreads();   // xs staged / previous tree's table reads done

        // Commit prefetched tables to smem; start next tree's LDG.
        if (tid < DNODES) nd[tid + 1] = nreg;
        cw[tid]       = c0reg;
        cw[tid + 256] = c1reg;
        if (tt + 1 < TGROUP) ldg_tables(tt + 1);
        __syncthreads();

        // Path levels 0..3 (scalar uint2 broadcasts; slot = node+1).
        uint2 n0 = nd[1], n1 = nd[a1 + 1], n2 = nd[a2 + 1], n3 = nd[a3 + 1];
        ull th0 = nodeth(n0.x, n0.y);
        ull th1 = nodeth(n1.x, n1.y);
        ull th2 = nodeth(n2.x, n2.y);
        ull th3 = nodeth(n3.x, n3.y);
        ull pre = mul2(mul2(ffma2(sg0, th0, H2), ffma2(sg1, th1, H2)),
                       ffma2(sg2, th2, H2));
        ull pA = mul2(pre, facn(th3));
        ull pB = mul2(pre, facp(th3));

        // Level 4: nodes 15+2s,16+2s -> slots 16+2s (uint4 at nd4[8+s]).
        ull q0, q1, q2, q3;
        {
            uint4 v = nd4[8 + s];
            ull ta = nodeth(v.x, v.y);
            ull tb = nodeth(v.z, v.w);
            q0 = mul2(pA, facn(ta)); q1 = mul2(pA, facp(ta));
            q2 = mul2(pB, facn(tb)); q3 = mul2(pB, facp(tb));
        }
        // Level 5: slots 32+4s -> nd4[16+2s], nd4[17+2s].
        ull r[8];
#pragma unroll
        for (int j = 0; j < 2; j++) {
            uint4 v = nd4[16 + 2 * s + j];
            ull ta = nodeth(v.x, v.y);
            ull tb = nodeth(v.z, v.w);
            ull qa = (j == 0) ? q0 : q2;
            ull qb = (j == 0) ? q1 : q3;
            r[4 * j + 0] = mul2(qa, facn(ta));
            r[4 * j + 1] = mul2(qa, facp(ta));
            r[4 * j + 2] = mul2(qb, facn(tb));
            r[4 * j + 3] = mul2(qb, facp(tb));
        }

        // Levels 6+7 interleaved per level-6 node pair (keeps regs low).
        // Level-7 contraction in (S,D) form: leafpair i7 contributes
        // u*S + (u*th)*D to the 8 classes.
        const ulonglong2* cwp = reinterpret_cast<const ulonglong2*>(cw) + (size_t)s * 64;
#pragma unroll
        for (int j = 0; j < 4; j++) {
            // Level 6 pair: slots 64+8s+2j -> nd4[32+4s+j].
            uint4 v6 = nd4[32 + 4 * s + j];
            ull t6a = nodeth(v6.x, v6.y);
            ull t6b = nodeth(v6.z, v6.w);
            ull uu[4];
            uu[0] = mul2(r[2 * j],     facn(t6a));
            uu[1] = mul2(r[2 * j],     facp(t6a));
            uu[2] = mul2(r[2 * j + 1], facn(t6b));
            uu[3] = mul2(r[2 * j + 1], facp(t6b));

            // Level 7: 4 nodes -> nd4[64+8s+2j], nd4[64+8s+2j+1].
            uint4 v7a = nd4[64 + 8 * s + 2 * j];
            uint4 v7b = nd4[65 + 8 * s + 2 * j];
            ull th7[4];
            th7[0] = nodeth(v7a.x, v7a.y);
            th7[1] = nodeth(v7a.z, v7a.w);
            th7[2] = nodeth(v7b.x, v7b.y);
            th7[3] = nodeth(v7b.z, v7b.w);
#pragma unroll
            for (int i = 0; i < 4; i++) {
                const int i7 = 4 * j + i;          // leaf pair within slice
                ull ut = mul2(uu[i], th7[i]);
                float uAf, uBf, utAf, utBf;
                upk2(uu[i], uAf, uBf);
                upk2(ut,    utAf, utBf);
                ulonglong2 S0 = cwp[4 * i7 + 0];   // S classes 0..3
                ulonglong2 S1 = cwp[4 * i7 + 1];   // S classes 4..7
                ulonglong2 D0 = cwp[4 * i7 + 2];   // D classes 0..3
                ulonglong2 D1 = cwp[4 * i7 + 3];   // D classes 4..7
                ull uA  = pk2(uAf,  uAf),  uB  = pk2(uBf,  uBf);
                ull utA = pk2(utAf, utAf), utB = pk2(utBf, utBf);
                accA[0] = ffma2(uA,  S0.x, accA[0]);
                accA[1] = ffma2(uA,  S0.y, accA[1]);
                accA[2] = ffma2(uA,  S1.x, accA[2]);
                accA[3] = ffma2(uA,  S1.y, accA[3]);
                accA[0] = ffma2(utA, D0.x, accA[0]);
                accA[1] = ffma2(utA, D0.y, accA[1]);
                accA[2] = ffma2(utA, D1.x, accA[2]);
                accA[3] = ffma2(utA, D1.y, accA[3]);
                accB[0] = ffma2(uB,  S0.x, accB[0]);
                accB[1] = ffma2(uB,  S0.y, accB[1]);
                accB[2] = ffma2(uB,  S1.x, accB[2]);
                accB[3] = ffma2(uB,  S1.y, accB[3]);
                accB[0] = ffma2(utB, D0.x, accB[0]);
                accB[1] = ffma2(utB, D0.y, accB[1]);
                accB[2] = ffma2(utB, D1.x, accB[2]);
                accB[3] = ffma2(utB, D1.y, accB[3]);
            }
        }
    }

    // Write out: lane owns rows bbase+lane and bbase+lane+32 for its slice.
    const float inv_t = 1.0f / (float)TREES;
    float aA[CCLS], aB[CCLS];
#pragma unroll
    for (int qq = 0; qq < 4; qq++) {
        upk2(accA[qq], aA[2 * qq], aA[2 * qq + 1]);
        upk2(accB[qq], aB[2 * qq], aB[2 * qq + 1]);
    }
    float* orowA = out + (size_t)(bbase + lane) * CCLS;
    float* orowB = out + (size_t)(bbase + lane + 32) * CCLS;
#pragma unroll
    for (int c = 0; c < CCLS; c++) {
        atomicAdd(&orowA[c], aA[c] * inv_t);
        atomicAdd(&orowB[c], aB[c] * inv_t);
    }
}

// ---------------------------------------------------------------------------
extern "C" void kernel_launch(void* const* d_in, const int* in_sizes, int n_in,
                              void* d_out, int out_size)
{
    // Identify inputs by element count (order per metadata: input, W1, b1,
    // Bpos, Bneg, Cw — Bpos/Bneg are structurally fixed and unused).
    const float* x  = nullptr;
    const float* W1 = nullptr;
    const float* b1 = nullptr;
    const float* Cw = nullptr;
    for (int i = 0; i < n_in; i++) {
        switch (in_sizes[i]) {
            case BATCH * MFEAT:          x  = (const float*)d_in[i]; break; // 2097152
            case TREES * DNODES * MFEAT: W1 = (const float*)d_in[i]; break; // 8355840
            case TREES * DNODES:         b1 = (const float*)d_in[i]; break; // 16320
            case TREES * KLEAF * CCLS:   Cw = (const float*)d_in[i]; break; // 131072
            default: break;                                                 // Bpos/Bneg
        }
    }
    float* out = (float*)d_out;

    // xs (64 KB) + nd (258 uint2) + cwsd (512 float4) = 75792 B -> 3 CTAs/SM.
    static const size_t smem_bytes = 512 * 32 * 4 + 258 * 8 + 512 * 16;
    cudaFuncSetAttribute(forest_kernel,
                         cudaFuncAttributeMaxDynamicSharedMemorySize,
                         (int)smem_bytes);

    cudaMemsetAsync(d_out, 0, (size_t)out_size * sizeof(float), 0);

    {
        int rows = TREES * DNODES;
        int warps_per_block = 8;
        int blocks = (rows + warps_per_block - 1) / warps_per_block;
        prep_kernel<<<blocks, warps_per_block * 32>>>(W1, b1);
    }
    {
        int n = TREES * (KLEAF / 2) * CCLS;
        cwprep_kernel<<<(n + 255) / 256, 256>>>(Cw);
    }

    dim3 grid(BATCH / ROWS, TREES / TGROUP);   // (64, 16) = 1024 CTAs
    forest_kernel<<<grid, 256, smem_bytes>>>(x, out);
}

// round 17
// speedup vs baseline: 1.1972x; 1.0596x over previous
#include <cuda_runtime.h>
#include <cuda_fp16.h>
#include <cuda_bf16.h>
#include <cstdint>

// Problem constants (fixed by the dataset).
#define TREES 64
#define DNODES 255      // internal nodes per tree (2^8 - 1)
#define KLEAF 256       // leaves per tree
#define MFEAT 512       // features
#define CCLS 8          // classes
#define BATCH 4096

// Blocking: CTA = 256 threads (8 warps = 8 leaf slices) over 64 batch rows.
// Lane l owns rows (bbase+l, bbase+l+32), packed as half2 in smem.
#define ROWS 64
#define TGROUP 4        // trees per CTA -> grid (64, 16) = 1024 CTAs

// Merged-prep block partition.
#define PREP_BLOCKS 2040     // warp-per-row: 16320 rows / 8 warps
#define CW_BLOCKS   32       // (t, i7) per thread: 8192 threads
#define OUT_BLOCKS  32       // zero 32768 floats via float4

// xs word index: (f<<5) | (l ^ ((f>>2)&31)).
//  - gather (fixed f, varying l): bank = l ^ c -> conflict-free
//  - staging (fixed l, lane k handles f=(i*32+k)*4+j): (f>>2)&31 = k ->
//    bank = l ^ k -> conflict-free STS as well.
__device__ __forceinline__ unsigned xword(unsigned f, unsigned l)
{
    return (f << 5) | (l ^ ((f >> 2) & 31u));
}

// Scratch (no cudaMalloc allowed).
// g_node[t*DNODES+d] = { precomputed-gather-byte-offset, half2{5*b1, 5*b1} }.
//   pre4 = (((f<<5) | ((f>>2)&31)) << 2); gather offset = pre4 ^ (lane<<2).
__device__ uint2 g_node[TREES * DNODES];
// g_cwsd: Cw transformed to leaf-pair (S, D) form:
//   for leaf pair (2*i7, 2*i7+1):  S_c = (cA_c + cB_c)/2,  D_c = (cB_c - cA_c)/2
//   layout [t][i7*16 + c] = S_c, [t][i7*16 + 8 + c] = D_c  (2048 floats/tree).
__device__ float g_cwsd[TREES * KLEAF * CCLS];

// ---------------------------------------------------------------------------
// Merged preprocess kernel (block-partitioned roles):
//   bid < PREP_BLOCKS                : W1 one-hot scan -> g_node (warp/row)
//   bid < PREP_BLOCKS+CW_BLOCKS      : Cw -> (S,D) leaf-pair form
//   else                             : zero the output buffer
// ---------------------------------------------------------------------------
__global__ void prep_kernel(const float* __restrict__ W1,
                            const float* __restrict__ b1,
                            const float* __restrict__ Cw,
                            float* __restrict__ out)
{
    const int bid = blockIdx.x;
    const int tid = threadIdx.x;

    if (bid < PREP_BLOCKS) {
        int row = bid * 8 + (tid >> 5);
        if (row < TREES * DNODES) {
            int lane = tid & 31;
            const float4* w4 = reinterpret_cast<const float4*>(W1 + (size_t)row * MFEAT);
            int idx = 0;
#pragma unroll
            for (int i = 0; i < 4; i++) {
                float4 v = w4[i * 32 + lane];
                int base = (i * 32 + lane) * 4;
                if (v.x != 0.0f) idx = base + 0;
                if (v.y != 0.0f) idx = base + 1;
                if (v.z != 0.0f) idx = base + 2;
                if (v.w != 0.0f) idx = base + 3;
            }
            idx = __reduce_max_sync(0xffffffffu, idx);
            if (lane == 0) {
                // sigmoid(10x+10b) = 0.5 + 0.5*tanh(5x+5b)
                __half   h  = __float2half(5.0f * b1[row]);
                __half2  h2 = __half2half2(h);
                unsigned f  = (unsigned)idx;
                unsigned pre4 = ((f << 5) | ((f >> 2) & 31u)) << 2;
                g_node[row] = make_uint2(pre4, *reinterpret_cast<unsigned*>(&h2));
            }
        }
    } else if (bid < PREP_BLOCKS + CW_BLOCKS) {
        // One (t, i7) leaf pair per thread: 16 contiguous floats in, 16 out.
        int i = (bid - PREP_BLOCKS) * 256 + tid;       // 0 .. 8191
        int i7 = i & 127;
        int t  = i >> 7;
        const float4* src = reinterpret_cast<const float4*>(
            Cw + (size_t)t * (KLEAF * CCLS) + (size_t)i7 * 16);
        float4 a0 = src[0], a1 = src[1];               // leaf 2*i7
        float4 b0 = src[2], b1v = src[3];              // leaf 2*i7+1
        float4* dst = reinterpret_cast<float4*>(
            g_cwsd + (size_t)t * (KLEAF * CCLS) + (size_t)i7 * 16);
        dst[0] = make_float4(0.5f * (a0.x + b0.x),  0.5f * (a0.y + b0.y),
                             0.5f * (a0.z + b0.z),  0.5f * (a0.w + b0.w));
        dst[1] = make_float4(0.5f * (a1.x + b1v.x), 0.5f * (a1.y + b1v.y),
                             0.5f * (a1.z + b1v.z), 0.5f * (a1.w + b1v.w));
        dst[2] = make_float4(0.5f * (b0.x - a0.x),  0.5f * (b0.y - a0.y),
                             0.5f * (b0.z - a0.z),  0.5f * (b0.w - a0.w));
        dst[3] = make_float4(0.5f * (b1v.x - a1.x), 0.5f * (b1v.y - a1.y),
                             0.5f * (b1v.z - a1.z), 0.5f * (b1v.w - a1.w));
    } else {
        int i = (bid - PREP_BLOCKS - CW_BLOCKS) * 256 + tid;   // float4 index
        reinterpret_cast<float4*>(out)[i] = make_float4(0.f, 0.f, 0.f, 0.f);
    }

    // Let the PDL-dependent forest kernel begin launching.
    cudaTriggerProgrammaticLaunchCompletion();
}

// th = tanh(z) via single MUFU.TANH (f32 — precision headroom).
__device__ __forceinline__ float tanhf_hw(float z)
{
    float r;
    asm("tanh.approx.f32 %0, %1;" : "=f"(r) : "f"(z));
    return r;
}

typedef unsigned long long ull;

__device__ __forceinline__ ull pk2(float lo, float hi)
{
    ull r;
    asm("mov.b64 %0, {%1, %2};" : "=l"(r) : "f"(lo), "f"(hi));
    return r;
}
__device__ __forceinline__ ull ffma2(ull a, ull b, ull c)
{
    ull d;
    asm("fma.rn.f32x2 %0, %1, %2, %3;" : "=l"(d) : "l"(a), "l"(b), "l"(c));
    return d;
}
__device__ __forceinline__ ull mul2(ull a, ull b)
{
    ull d;
    asm("mul.rn.f32x2 %0, %1, %2;" : "=l"(d) : "l"(a), "l"(b));
    return d;
}
__device__ __forceinline__ void upk2(ull v, float& lo, float& hi)
{
    asm("mov.b64 {%0, %1}, %2;" : "=f"(lo), "=f"(hi) : "l"(v));
}

#define H2  0x3F0000003F000000ull   // {0.5f, 0.5f}
#define NH2 0xBF000000BF000000ull   // {-0.5f, -0.5f}

// ---------------------------------------------------------------------------
// Main kernel (PDL secondary). Stages x (independent of prep outputs), THEN
// cudaGridDependencySynchronize(), then consumes g_node/g_cwsd. 256 threads
// (8 warps = 8 slices), 64 rows as 32 half2 row-pairs in a fully
// conflict-free smem layout. Node eval: XOR + LDS.32 + HFMA2 + 2 cvt +
// 2 f32 tanh. Leaf contraction in (S,D) form. Next tree's tables prefetched
// into registers during compute.
// ---------------------------------------------------------------------------
__global__ __launch_bounds__(256, 3)
void forest_kernel(const float* __restrict__ x,
                   float* __restrict__ out)
{
    extern __shared__ unsigned smem_u[];
    unsigned* xs  = smem_u;                                       // 512*32 words (64 KB)
    uint2*    nd  = reinterpret_cast<uint2*>(smem_u + 512 * 32);  // 258 slots (node d -> d+1)
    float4*   cw  = reinterpret_cast<float4*>(smem_u + 512 * 32 + 258 * 2); // 512 float4

    const int tid   = threadIdx.x;
    const int lane  = tid & 31;
    const int s     = tid >> 5;          // warp id = leaf slice
    const int bbase = blockIdx.x * ROWS;
    const int tbase = blockIdx.y * TGROUP;
    const unsigned lane4 = (unsigned)lane << 2;

    // Stage 64 x-rows as half2 row-pairs (conflict-free STS via xword).
    // Independent of the prep kernel's outputs -> runs before gridsync.
    {
        const float4* x4 = reinterpret_cast<const float4*>(x);
#pragma unroll
        for (int rp = 0; rp < 4; rp++) {
            const int l = s * 4 + rp;              // row-pair id = low row
            const float4* rowA = x4 + (size_t)(bbase + l) * 128;
            const float4* rowB = x4 + (size_t)(bbase + l + 32) * 128;
#pragma unroll
            for (int i = 0; i < 4; i++) {
                float4 a = rowA[i * 32 + lane];
                float4 b = rowB[i * 32 + lane];
                const float av[4] = {a.x, a.y, a.z, a.w};
                const float bv[4] = {b.x, b.y, b.z, b.w};
#pragma unroll
                for (int j = 0; j < 4; j++) {
                    unsigned f = (unsigned)((i * 32 + lane) * 4 + j);
                    __half2 h2 = __floats2half2_rn(av[j], bv[j]);
                    xs[xword(f, (unsigned)l)] = *reinterpret_cast<unsigned*>(&h2);
                }
            }
        }
    }

    // Wait for prep's g_node / g_cwsd / zeroed out to be visible.
    cudaGridDependencySynchronize();

    // Warp-constant path ids / sign splats (levels 0..2); level-3 = 7+s.
    const ull sg0 = (s & 4) ? H2 : NH2;
    const ull sg1 = (s & 2) ? H2 : NH2;
    const ull sg2 = (s & 1) ? H2 : NH2;
    const int a1 = 1 + (s >> 2);
    const int a2 = 3 + (s >> 1);
    const int a3 = 7 + s;

    const __half2 five2 = __floats2half2_rn(5.0f, 5.0f);

    ull accA[4] = {0, 0, 0, 0};
    ull accB[4] = {0, 0, 0, 0};

    // Evaluate one node for the lane's row pair: XOR + LDS.32 + HFMA2 +
    // 2 cvt + 2 f32 tanh; result packed {rowA, rowB} as f32x2.
    auto nodeth = [&](unsigned pre4, unsigned tbbits) -> ull {
        unsigned xb = *reinterpret_cast<const unsigned*>(
            reinterpret_cast<const char*>(xs) + (pre4 ^ lane4));
        __half2 xv = *reinterpret_cast<__half2*>(&xb);
        __half2 tb = *reinterpret_cast<__half2*>(&tbbits);
        __half2 z2 = __hfma2(xv, five2, tb);
        float2 zf = __half22float2(z2);
        return pk2(tanhf_hw(zf.x), tanhf_hw(zf.y));
    };
    auto facn = [&](ull th) -> ull { return ffma2(NH2, th, H2); };
    auto facp = [&](ull th) -> ull { return ffma2(H2,  th, H2); };

    const uint4* nd4 = reinterpret_cast<const uint4*>(nd);

    // Register prefetch buffers for the per-tree tables.
    uint2  nreg = make_uint2(0u, 0u);
    float4 c0reg, c1reg;
    auto ldg_tables = [&](int t_idx) {
        const int t = tbase + t_idx;
        if (tid < DNODES) nreg = g_node[(size_t)t * DNODES + tid];
        const float4* cws = reinterpret_cast<const float4*>(
            g_cwsd + (size_t)t * (KLEAF * CCLS));
        c0reg = cws[tid];
        c1reg = cws[tid + 256];
    };

    ldg_tables(0);

#pragma unroll 1
    for (int tt = 0; tt < TGROUP; tt++) {
        __syncthreads();   // xs staged / previous tree's table reads done

        // Commit prefetched tables to smem; start next tree's LDG.
        if (tid < DNODES) nd[tid + 1] = nreg;
        cw[tid]       = c0reg;
        cw[tid + 256] = c1reg;
        if (tt + 1 < TGROUP) ldg_tables(tt + 1);
        __syncthreads();

        // Path levels 0..3 (scalar uint2 broadcasts; slot = node+1).
        uint2 n0 = nd[1], n1 = nd[a1 + 1], n2 = nd[a2 + 1], n3 = nd[a3 + 1];
        ull th0 = nodeth(n0.x, n0.y);
        ull th1 = nodeth(n1.x, n1.y);
        ull th2 = nodeth(n2.x, n2.y);
        ull th3 = nodeth(n3.x, n3.y);
        ull pre = mul2(mul2(ffma2(sg0, th0, H2), ffma2(sg1, th1, H2)),
                       ffma2(sg2, th2, H2));
        ull pA = mul2(pre, facn(th3));
        ull pB = mul2(pre, facp(th3));

        // Level 4: nodes 15+2s,16+2s -> slots 16+2s (uint4 at nd4[8+s]).
        ull q0, q1, q2, q3;
        {
            uint4 v = nd4[8 + s];
            ull ta = nodeth(v.x, v.y);
            ull tb = nodeth(v.z, v.w);
            q0 = mul2(pA, facn(ta)); q1 = mul2(pA, facp(ta));
            q2 = mul2(pB, facn(tb)); q3 = mul2(pB, facp(tb));
        }
        // Level 5: slots 32+4s -> nd4[16+2s], nd4[17+2s].
        ull r[8];
#pragma unroll
        for (int j = 0; j < 2; j++) {
            uint4 v = nd4[16 + 2 * s + j];
            ull ta = nodeth(v.x, v.y);
            ull tb = nodeth(v.z, v.w);
            ull qa = (j == 0) ? q0 : q2;
            ull qb = (j == 0) ? q1 : q3;
            r[4 * j + 0] = mul2(qa, facn(ta));
            r[4 * j + 1] = mul2(qa, facp(ta));
            r[4 * j + 2] = mul2(qb, facn(tb));
            r[4 * j + 3] = mul2(qb, facp(tb));
        }

        // Levels 6+7 interleaved per level-6 node pair (keeps regs low).
        // Level-7 contraction in (S,D) form: leafpair i7 contributes
        // u*S + (u*th)*D to the 8 classes.
        const ulonglong2* cwp = reinterpret_cast<const ulonglong2*>(cw) + (size_t)s * 64;
#pragma unroll
        for (int j = 0; j < 4; j++) {
            // Level 6 pair: slots 64+8s+2j -> nd4[32+4s+j].
            uint4 v6 = nd4[32 + 4 * s + j];
            ull t6a = nodeth(v6.x, v6.y);
            ull t6b = nodeth(v6.z, v6.w);
            ull uu[4];
            uu[0] = mul2(r[2 * j],     facn(t6a));
            uu[1] = mul2(r[2 * j],     facp(t6a));
            uu[2] = mul2(r[2 * j + 1], facn(t6b));
            uu[3] = mul2(r[2 * j + 1], facp(t6b));

            // Level 7: 4 nodes -> nd4[64+8s+2j], nd4[64+8s+2j+1].
            uint4 v7a = nd4[64 + 8 * s + 2 * j];
            uint4 v7b = nd4[65 + 8 * s + 2 * j];
            ull th7[4];
            th7[0] = nodeth(v7a.x, v7a.y);
            th7[1] = nodeth(v7a.z, v7a.w);
            th7[2] = nodeth(v7b.x, v7b.y);
            th7[3] = nodeth(v7b.z, v7b.w);
#pragma unroll
            for (int i = 0; i < 4; i++) {
                const int i7 = 4 * j + i;          // leaf pair within slice
                ull ut = mul2(uu[i], th7[i]);
                float uAf, uBf, utAf, utBf;
                upk2(uu[i], uAf, uBf);
                upk2(ut,    utAf, utBf);
                ulonglong2 S0 = cwp[4 * i7 + 0];   // S classes 0..3
                ulonglong2 S1 = cwp[4 * i7 + 1];   // S classes 4..7
                ulonglong2 D0 = cwp[4 * i7 + 2];   // D classes 0..3
                ulonglong2 D1 = cwp[4 * i7 + 3];   // D classes 4..7
                ull uA  = pk2(uAf,  uAf),  uB  = pk2(uBf,  uBf);
                ull utA = pk2(utAf, utAf), utB = pk2(utBf, utBf);
                accA[0] = ffma2(uA,  S0.x, accA[0]);
                accA[1] = ffma2(uA,  S0.y, accA[1]);
                accA[2] = ffma2(uA,  S1.x, accA[2]);
                accA[3] = ffma2(uA,  S1.y, accA[3]);
                accA[0] = ffma2(utA, D0.x, accA[0]);
                accA[1] = ffma2(utA, D0.y, accA[1]);
                accA[2] = ffma2(utA, D1.x, accA[2]);
                accA[3] = ffma2(utA, D1.y, accA[3]);
                accB[0] = ffma2(uB,  S0.x, accB[0]);
                accB[1] = ffma2(uB,  S0.y, accB[1]);
                accB[2] = ffma2(uB,  S1.x, accB[2]);
                accB[3] = ffma2(uB,  S1.y, accB[3]);
                accB[0] = ffma2(utB, D0.x, accB[0]);
                accB[1] = ffma2(utB, D0.y, accB[1]);
                accB[2] = ffma2(utB, D1.x, accB[2]);
                accB[3] = ffma2(utB, D1.y, accB[3]);
            }
        }
    }

    // Write out: lane owns rows bbase+lane and bbase+lane+32 for its slice.
    const float inv_t = 1.0f / (float)TREES;
    float aA[CCLS], aB[CCLS];
#pragma unroll
    for (int qq = 0; qq < 4; qq++) {
        upk2(accA[qq], aA[2 * qq], aA[2 * qq + 1]);
        upk2(accB[qq], aB[2 * qq], aB[2 * qq + 1]);
    }
    float* orowA = out + (size_t)(bbase + lane) * CCLS;
    float* orowB = out + (size_t)(bbase + lane + 32) * CCLS;
#pragma unroll
    for (int c = 0; c < CCLS; c++) {
        atomicAdd(&orowA[c], aA[c] * inv_t);
        atomicAdd(&orowB[c], aB[c] * inv_t);
    }
}

// ---------------------------------------------------------------------------
extern "C" void kernel_launch(void* const* d_in, const int* in_sizes, int n_in,
                              void* d_out, int out_size)
{
    // Identify inputs by element count (order per metadata: input, W1, b1,
    // Bpos, Bneg, Cw — Bpos/Bneg are structurally fixed and unused).
    const float* x  = nullptr;
    const float* W1 = nullptr;
    const float* b1 = nullptr;
    const float* Cw = nullptr;
    for (int i = 0; i < n_in; i++) {
        switch (in_sizes[i]) {
            case BATCH * MFEAT:          x  = (const float*)d_in[i]; break; // 2097152
            case TREES * DNODES * MFEAT: W1 = (const float*)d_in[i]; break; // 8355840
            case TREES * DNODES:         b1 = (const float*)d_in[i]; break; // 16320
            case TREES * KLEAF * CCLS:   Cw = (const float*)d_in[i]; break; // 131072
            default: break;                                                 // Bpos/Bneg
        }
    }
    float* out = (float*)d_out;

    // xs (64 KB) + nd (258 uint2) + cwsd (512 float4) = 75792 B -> 3 CTAs/SM.
    static const size_t smem_bytes = 512 * 32 * 4 + 258 * 8 + 512 * 16;
    cudaFuncSetAttribute(forest_kernel,
                         cudaFuncAttributeMaxDynamicSharedMemorySize,
                         (int)smem_bytes);

    // Merged preprocess (also zeroes out) ...
    prep_kernel<<<PREP_BLOCKS + CW_BLOCKS + OUT_BLOCKS, 256>>>(W1, b1, Cw, out);

    // ... then forest as a PDL secondary: its x-staging overlaps prep's tail;
    // cudaGridDependencySynchronize() inside orders the table reads.
    cudaLaunchConfig_t cfg = {};
    cfg.gridDim  = dim3(BATCH / ROWS, TREES / TGROUP);   // (64, 16)
    cfg.blockDim = dim3(256, 1, 1);
    cfg.dynamicSmemBytes = (unsigned)smem_bytes;
    cfg.stream = 0;
    cudaLaunchAttribute attrs[1];
    attrs[0].id = cudaLaunchAttributeProgrammaticStreamSerialization;
    attrs[0].val.programmaticStreamSerializationAllowed = 1;
    cfg.attrs = attrs;
    cfg.numAttrs = 1;
    cudaLaunchKernelEx(&cfg, forest_kernel, x, out);
}